// round 3
// baseline (speedup 1.0000x reference)
#include <cuda_runtime.h>
#include <math.h>
#include <stdint.h>

#define NN 8000
#define EE 24000
#define EAA 32000
#define BB 256
#define ATOMD 133
#define BONDD 14
#define HD 256
#define NHEADS 8
#define HHD 2048
#define NLAYERS 5

// ---------------- scratch (device globals; no allocation allowed) -------------
__device__ float g_h[NN * HD];            // node features
__device__ float g_out[NN * HD];          // message accumulator
__device__ float g_xl[NN * HHD];          // h @ Wl
__device__ float g_xr[NN * HHD];          // h @ Wr
__device__ float g_score[EAA * NHEADS];   // scores, then exp(score - m)
__device__ unsigned g_m[NN * NHEADS];     // segment max (encoded)
__device__ float g_s[NN * NHEADS];        // segment sum of exp
__device__ float g_deg[NN];
__device__ float g_loopsum[NN * BONDD];
__device__ float g_loop[NN * BONDD];      // self-loop edge attr (mean of incoming)
__device__ float g_gate[NN];
__device__ float g_ge[NN];
__device__ unsigned g_gm[BB];
__device__ float g_gs[BB];

// monotonic float<->uint map for atomicMax on floats
__device__ __forceinline__ unsigned fenc(float f) {
    unsigned u = __float_as_uint(f);
    return (u & 0x80000000u) ? ~u : (u | 0x80000000u);
}
__device__ __forceinline__ float fdec(unsigned u) {
    u = (u & 0x80000000u) ? (u & 0x7FFFFFFFu) : ~u;
    return __uint_as_float(u);
}
#define ENC_NEG_INF 0x007FFFFFu  // fenc(-inf)

__device__ __forceinline__ uint32_t f2tf32(float f) {
    uint32_t r;
    asm("cvt.rna.tf32.f32 %0, %1;" : "=r"(r) : "f"(f));
    return r;
}

// ---------------- pre: self-loop attr = mean of incoming edge_attr ------------
__global__ void k_init_pre() {
    int i = blockIdx.x * blockDim.x + threadIdx.x;
    if (i < NN * BONDD) g_loopsum[i] = 0.f;
    if (i < NN) g_deg[i] = 0.f;
}

__global__ void k_degattr(const int* __restrict__ dst, const float* __restrict__ ea) {
    int j = blockIdx.x * blockDim.x + threadIdx.x;
    if (j >= EE * BONDD) return;
    int e = j / BONDD, b = j - e * BONDD;
    int d = dst[e];
    atomicAdd(&g_loopsum[d * BONDD + b], ea[j]);
    if (b == 0) atomicAdd(&g_deg[d], 1.f);
}

__global__ void k_loopdiv() {
    int j = blockIdx.x * blockDim.x + threadIdx.x;
    if (j >= NN * BONDD) return;
    int n = j / BONDD;
    g_loop[j] = g_loopsum[j] / fmaxf(g_deg[n], 1.f);
}

// ---------------- atom embedding: relu(LN(x @ W + b)) ------------------------
__global__ void k_embed(const float* __restrict__ x, const float* __restrict__ W,
                        const float* __restrict__ b, const float* __restrict__ g,
                        const float* __restrict__ be) {
    int n = blockIdx.x, tid = threadIdx.x;  // 256 threads
    __shared__ float sx[ATOMD];
    __shared__ float rs[8], rq[8];
    if (tid < ATOMD) sx[tid] = x[n * ATOMD + tid];
    __syncthreads();
    float acc = b[tid];
    for (int k = 0; k < ATOMD; k++) acc += sx[k] * W[k * HD + tid];
    float a = acc, q = acc * acc;
    #pragma unroll
    for (int o = 16; o; o >>= 1) {
        a += __shfl_xor_sync(~0u, a, o);
        q += __shfl_xor_sync(~0u, q, o);
    }
    int lane = tid & 31, w = tid >> 5;
    if (!lane) { rs[w] = a; rq[w] = q; }
    __syncthreads();
    float sum = 0.f, sq = 0.f;
    #pragma unroll
    for (int i = 0; i < 8; i++) { sum += rs[i]; sq += rq[i]; }
    float mean = sum * (1.f / HD);
    float var = sq * (1.f / HD) - mean * mean;
    float y = (acc - mean) * rsqrtf(var + 1e-5f) * g[tid] + be[tid];
    g_h[n * HD + tid] = fmaxf(y, 0.f);
}

// ---------------- TF32 tensor-core GEMM ---------------------------------------
// C = g_h[8000,256] @ W[256,2048], grid.z selects (Wl -> g_xl) / (Wr -> g_xr).
// Tile 128x128x32, 8 warps (4 M x 2 N), warp tile 32x64, mma.m16n8k8.tf32.
#define BM 128
#define BN 128
#define BK 32
#define SPAD 4   // smem row padding (floats)

__global__ void __launch_bounds__(256) k_gemm_tc(const float* __restrict__ Wl,
                                                 const float* __restrict__ Wr) {
    __shared__ float As[BK][BM + SPAD];   // k-major A
    __shared__ float Bs[BK][BN + SPAD];   // k-major B

    const float* W = blockIdx.z ? Wr : Wl;
    float* C = blockIdx.z ? g_xr : g_xl;

    const int t = threadIdx.x;
    const int lane = t & 31;
    const int warp = t >> 5;
    const int wm = warp & 3;            // 0..3 -> M offset warp*32
    const int wn = warp >> 2;           // 0..1 -> N offset warp*64
    const int m0 = blockIdx.y * BM;
    const int n0 = blockIdx.x * BN;
    const int gr = lane >> 2;           // group id 0..7
    const int tg = lane & 3;            // thread-in-group 0..3

    float c[2][8][4];
    #pragma unroll
    for (int i = 0; i < 2; i++)
        #pragma unroll
        for (int j = 0; j < 8; j++)
            #pragma unroll
            for (int k = 0; k < 4; k++) c[i][j][k] = 0.f;

    for (int k0 = 0; k0 < HD; k0 += BK) {
        // --- load A tile (transpose to k-major): 128x32 floats, 4 passes ---
        #pragma unroll
        for (int p = 0; p < 4; p++) {
            int idx = p * 256 + t;      // 0..1023
            int m = idx >> 3;           // 0..127
            int kq = idx & 7;           // float4 index along k
            float4 v = make_float4(0.f, 0.f, 0.f, 0.f);
            if (m0 + m < NN)
                v = *(const float4*)&g_h[(m0 + m) * HD + k0 + kq * 4];
            As[kq * 4 + 0][m] = v.x;
            As[kq * 4 + 1][m] = v.y;
            As[kq * 4 + 2][m] = v.z;
            As[kq * 4 + 3][m] = v.w;
        }
        // --- load B tile: 32x128 floats, natural layout, 4 passes ---
        #pragma unroll
        for (int p = 0; p < 4; p++) {
            int idx = p * 256 + t;
            int kk = idx >> 5;          // 0..31
            int nq = idx & 31;          // float4 col
            *(float4*)&Bs[kk][nq * 4] =
                *(const float4*)&W[(size_t)(k0 + kk) * HHD + n0 + nq * 4];
        }
        __syncthreads();

        #pragma unroll
        for (int ks = 0; ks < BK / 8; ks++) {
            int kb = ks * 8;
            uint32_t a[2][4];
            #pragma unroll
            for (int im = 0; im < 2; im++) {
                int mr = wm * 32 + im * 16;
                a[im][0] = f2tf32(As[kb + tg][mr + gr]);
                a[im][1] = f2tf32(As[kb + tg][mr + gr + 8]);
                a[im][2] = f2tf32(As[kb + tg + 4][mr + gr]);
                a[im][3] = f2tf32(As[kb + tg + 4][mr + gr + 8]);
            }
            #pragma unroll
            for (int jn = 0; jn < 8; jn++) {
                int nc = wn * 64 + jn * 8 + gr;
                uint32_t b0 = f2tf32(Bs[kb + tg][nc]);
                uint32_t b1 = f2tf32(Bs[kb + tg + 4][nc]);
                #pragma unroll
                for (int im = 0; im < 2; im++) {
                    asm volatile(
                        "mma.sync.aligned.m16n8k8.row.col.f32.tf32.tf32.f32 "
                        "{%0,%1,%2,%3}, {%4,%5,%6,%7}, {%8,%9}, {%0,%1,%2,%3};\n"
                        : "+f"(c[im][jn][0]), "+f"(c[im][jn][1]),
                          "+f"(c[im][jn][2]), "+f"(c[im][jn][3])
                        : "r"(a[im][0]), "r"(a[im][1]), "r"(a[im][2]), "r"(a[im][3]),
                          "r"(b0), "r"(b1));
                }
            }
        }
        __syncthreads();
    }

    // --- epilogue ---
    #pragma unroll
    for (int im = 0; im < 2; im++) {
        #pragma unroll
        for (int jn = 0; jn < 8; jn++) {
            int row = m0 + wm * 32 + im * 16 + gr;
            int col = n0 + wn * 64 + jn * 8 + 2 * tg;
            if (row < NN) {
                C[(size_t)row * HHD + col]     = c[im][jn][0];
                C[(size_t)row * HHD + col + 1] = c[im][jn][1];
            }
            if (row + 8 < NN) {
                C[(size_t)(row + 8) * HHD + col]     = c[im][jn][2];
                C[(size_t)(row + 8) * HHD + col + 1] = c[im][jn][3];
            }
        }
    }
}

// ---------------- per-layer zero/init -----------------------------------------
__global__ void k_init_layer() {
    int i = blockIdx.x * blockDim.x + threadIdx.x;
    if (i < NN * HD) g_out[i] = 0.f;
    if (i < NN * NHEADS) { g_s[i] = 0.f; g_m[i] = ENC_NEG_INF; }
}

// ---------------- edge score: leaky(xl[s]+xr[d]+ea@We) . att  -----------------
__global__ void k_score(const int* __restrict__ src, const int* __restrict__ dst,
                        const float* __restrict__ edge_attr,
                        const float* __restrict__ We_l, const float* __restrict__ att_l) {
    int e = blockIdx.x, tid = threadIdx.x;
    __shared__ float sea[BONDD];
    __shared__ float wsum[NHEADS * 8];
    int s, d;
    const float* ea;
    if (e < EE) { s = src[e]; d = dst[e]; ea = edge_attr + e * BONDD; }
    else        { s = d = e - EE;          ea = g_loop + (e - EE) * BONDD; }
    if (tid < BONDD) sea[tid] = ea[tid];
    __syncthreads();
    const float* xlrow = g_xl + (size_t)s * HHD;
    const float* xrrow = g_xr + (size_t)d * HHD;
    float part[NHEADS];
    #pragma unroll
    for (int h = 0; h < NHEADS; h++) {
        int cc = h * HD + tid;
        float eev = 0.f;
        #pragma unroll
        for (int b = 0; b < BONDD; b++) eev += sea[b] * We_l[b * HHD + cc];
        float v = xlrow[cc] + xrrow[cc] + eev;
        v = v > 0.f ? v : 0.2f * v;
        part[h] = v * att_l[cc];
    }
    int lane = tid & 31, w = tid >> 5;
    #pragma unroll
    for (int h = 0; h < NHEADS; h++) {
        float v = part[h];
        #pragma unroll
        for (int o = 16; o; o >>= 1) v += __shfl_xor_sync(~0u, v, o);
        if (!lane) wsum[h * 8 + w] = v;
    }
    __syncthreads();
    if (tid < NHEADS) {
        float v = 0.f;
        #pragma unroll
        for (int w2 = 0; w2 < 8; w2++) v += wsum[tid * 8 + w2];
        g_score[e * NHEADS + tid] = v;
        atomicMax(&g_m[d * NHEADS + tid], fenc(v));
    }
}

// ---------------- exp(score - max) + segment sum ------------------------------
__global__ void k_expsum(const int* __restrict__ dst) {
    int j = blockIdx.x * blockDim.x + threadIdx.x;
    if (j >= EAA * NHEADS) return;
    int e = j / NHEADS, h = j - e * NHEADS;
    int d = (e < EE) ? dst[e] : (e - EE);
    float ex = expf(g_score[j] - fdec(g_m[d * NHEADS + h]));
    g_score[j] = ex;
    atomicAdd(&g_s[d * NHEADS + h], ex);
}

// ---------------- message: out[d] += mean_h( xl[s,h,:] * alpha[e,h] ) ---------
__global__ void k_message(const int* __restrict__ src, const int* __restrict__ dst) {
    int e = blockIdx.x, tid = threadIdx.x;
    __shared__ float alpha[NHEADS];
    int s, d;
    if (e < EE) { s = src[e]; d = dst[e]; }
    else        { s = d = e - EE; }
    if (tid < NHEADS)
        alpha[tid] = g_score[e * NHEADS + tid] / g_s[d * NHEADS + tid];
    __syncthreads();
    const float* xlrow = g_xl + (size_t)s * HHD;
    float acc = 0.f;
    #pragma unroll
    for (int h = 0; h < NHEADS; h++) acc += xlrow[h * HD + tid] * alpha[h];
    atomicAdd(&g_out[d * HD + tid], 0.125f * acc);
}

// ---------------- residual + LayerNorm ----------------------------------------
__global__ void k_resln(const float* __restrict__ bias_l, const float* __restrict__ g,
                        const float* __restrict__ be) {
    int n = blockIdx.x, tid = threadIdx.x;
    __shared__ float rs[8], rq[8];
    float v = g_out[n * HD + tid] + bias_l[tid] + g_h[n * HD + tid];
    float a = v, q = v * v;
    #pragma unroll
    for (int o = 16; o; o >>= 1) {
        a += __shfl_xor_sync(~0u, a, o);
        q += __shfl_xor_sync(~0u, q, o);
    }
    int lane = tid & 31, w = tid >> 5;
    if (!lane) { rs[w] = a; rq[w] = q; }
    __syncthreads();
    float sum = 0.f, sq = 0.f;
    #pragma unroll
    for (int i = 0; i < 8; i++) { sum += rs[i]; sq += rq[i]; }
    float mean = sum * (1.f / HD);
    float var = sq * (1.f / HD) - mean * mean;
    g_h[n * HD + tid] = (v - mean) * rsqrtf(var + 1e-5f) * g[tid] + be[tid];
}

// ---------------- readout -----------------------------------------------------
__global__ void k_initread(float* __restrict__ out) {
    int i = blockIdx.x * blockDim.x + threadIdx.x;
    if (i < BB * HD) out[i] = 0.f;
    if (i < BB) { g_gm[i] = ENC_NEG_INF; g_gs[i] = 0.f; }
}

__global__ void k_gate(const float* __restrict__ W1, const float* __restrict__ b1,
                       const float* __restrict__ W2, const float* __restrict__ b2,
                       const int* __restrict__ batch) {
    int n = blockIdx.x, tid = threadIdx.x;  // 128 threads
    __shared__ float sh[HD];
    __shared__ float rs[4];
    sh[tid] = g_h[n * HD + tid];
    sh[tid + 128] = g_h[n * HD + tid + 128];
    __syncthreads();
    float acc = b1[tid];
    for (int k = 0; k < HD; k++) acc += sh[k] * W1[k * 128 + tid];
    float part = fmaxf(acc, 0.f) * W2[tid];
    #pragma unroll
    for (int o = 16; o; o >>= 1) part += __shfl_xor_sync(~0u, part, o);
    int lane = tid & 31, w = tid >> 5;
    if (!lane) rs[w] = part;
    __syncthreads();
    if (tid == 0) {
        float gate = rs[0] + rs[1] + rs[2] + rs[3] + b2[0];
        g_gate[n] = gate;
        atomicMax(&g_gm[batch[n]], fenc(gate));
    }
}

__global__ void k_gexp(const int* __restrict__ batch) {
    int n = blockIdx.x * blockDim.x + threadIdx.x;
    if (n >= NN) return;
    int b = batch[n];
    float ge = expf(g_gate[n] - fdec(g_gm[b]));
    g_ge[n] = ge;
    atomicAdd(&g_gs[b], ge);
}

__global__ void k_readout(const int* __restrict__ batch, float* __restrict__ out) {
    int n = blockIdx.x, tid = threadIdx.x;
    int b = batch[n];
    float w = g_ge[n] / fmaxf(g_gs[b], 1e-16f);
    atomicAdd(&out[b * HD + tid], w * g_h[n * HD + tid]);
}

// ---------------- launcher ----------------------------------------------------
extern "C" void kernel_launch(void* const* d_in, const int* in_sizes, int n_in,
                              void* d_out, int out_size) {
    const float* x         = (const float*)d_in[0];
    const float* edge_attr = (const float*)d_in[1];
    const float* emb_W     = (const float*)d_in[2];
    const float* emb_b     = (const float*)d_in[3];
    const float* emb_g     = (const float*)d_in[4];
    const float* emb_beta  = (const float*)d_in[5];
    const float* Wl        = (const float*)d_in[6];
    const float* Wr        = (const float*)d_in[7];
    const float* We        = (const float*)d_in[8];
    const float* att       = (const float*)d_in[9];
    const float* bias      = (const float*)d_in[10];
    const float* ln_g      = (const float*)d_in[11];
    const float* ln_b      = (const float*)d_in[12];
    const float* g1W       = (const float*)d_in[13];
    const float* g1b       = (const float*)d_in[14];
    const float* g2W       = (const float*)d_in[15];
    const float* g2b       = (const float*)d_in[16];
    const int* edge_index  = (const int*)d_in[17];
    const int* batch       = (const int*)d_in[18];
    const int* src = edge_index;
    const int* dst = edge_index + EE;
    float* out = (float*)d_out;

    k_init_pre<<<(NN * BONDD + 255) / 256, 256>>>();
    k_degattr<<<(EE * BONDD + 255) / 256, 256>>>(dst, edge_attr);
    k_loopdiv<<<(NN * BONDD + 255) / 256, 256>>>();
    k_embed<<<NN, HD>>>(x, emb_W, emb_b, emb_g, emb_beta);

    dim3 gg(HHD / BN, (NN + BM - 1) / BM, 2);
    for (int l = 0; l < NLAYERS; l++) {
        k_init_layer<<<(NN * HD + 255) / 256, 256>>>();
        k_gemm_tc<<<gg, 256>>>(Wl + (size_t)l * HD * HHD, Wr + (size_t)l * HD * HHD);
        k_score<<<EAA, HD>>>(src, dst, edge_attr,
                             We + (size_t)l * BONDD * HHD,
                             att + (size_t)l * NHEADS * HD);
        k_expsum<<<(EAA * NHEADS + 255) / 256, 256>>>(dst);
        k_message<<<EAA, HD>>>(src, dst);
        k_resln<<<NN, HD>>>(bias + l * HD, ln_g + l * HD, ln_b + l * HD);
    }

    k_initread<<<(BB * HD + 255) / 256, 256>>>(out);
    k_gate<<<NN, 128>>>(g1W, g1b, g2W, g2b, batch);
    k_gexp<<<(NN + 255) / 256, 256>>>(batch);
    k_readout<<<NN, HD>>>(batch, out);
}

// round 6
// speedup vs baseline: 2.0218x; 2.0218x over previous
#include <cuda_runtime.h>
#include <math.h>
#include <stdint.h>

#define NN 8000
#define EE 24000
#define EAA 32000
#define BB 256
#define ATOMD 133
#define BONDD 14
#define HD 256
#define NHEADS 8
#define HHD 2048
#define NLAYERS 5

#define MBLK 504                 // ceil(8064/16) m-fragment blocks
#define WELEM (HD * HHD)         // 524288 floats per weight matrix

// ---------------- scratch (device globals; no allocation allowed) -------------
__device__ float g_h[NN * HD];
__device__ float g_out[NN * HD];
__device__ float g_xl[NN * HHD];
__device__ float g_xr[NN * HHD];
__device__ float g_score[EAA * NHEADS];
__device__ unsigned g_m[NN * NHEADS];
__device__ float g_s[NN * NHEADS];
__device__ float g_deg[NN];
__device__ float g_loopsum[NN * BONDD];
__device__ float g_loop[NN * BONDD];
__device__ float g_gate[NN];
__device__ float g_ge[NN];
__device__ unsigned g_gm[BB];
__device__ float g_gs[BB];
// tf32-rounded, mma-fragment-major copies
__device__ float g_hf[MBLK * 32 * 128];     // A fragments: 8.3 MB
__device__ float g_Wf[10 * WELEM];          // B fragments: 21 MB

__device__ __forceinline__ unsigned fenc(float f) {
    unsigned u = __float_as_uint(f);
    return (u & 0x80000000u) ? ~u : (u | 0x80000000u);
}
__device__ __forceinline__ float fdec(unsigned u) {
    u = (u & 0x80000000u) ? (u & 0x7FFFFFFFu) : ~u;
    return __uint_as_float(u);
}
#define ENC_NEG_INF 0x007FFFFFu

__device__ __forceinline__ float tf32r(float f) {
    uint32_t u;
    asm("cvt.rna.tf32.f32 %0, %1;" : "=r"(u) : "f"(f));
    return __uint_as_float(u);
}

// A-fragment store: element (m, k) of h -> fragment-major global layout.
// block = (m>>4)*32 + (k>>3); within 16x8 block: lane=(m&7)*4+(k&3),
// slot = ((m>>3)&1) | (((k>>2)&1)<<1); offset = block*128 + lane*4 + slot.
__device__ __forceinline__ void store_frag_h(int m, int k, float v) {
    int blk = (m >> 4) * 32 + (k >> 3);
    int lane = (m & 7) * 4 + (k & 3);
    int slot = ((m >> 3) & 1) | (((k >> 2) & 1) << 1);
    g_hf[blk * 128 + lane * 4 + slot] = tf32r(v);
}

#define CP16(dst, src) \
    asm volatile("cp.async.cg.shared.global [%0], [%1], 16;" \
                 :: "r"(dst), "l"(src) : "memory")

__device__ __forceinline__ uint32_t smem_u32(const void* p) {
    uint32_t a;
    asm("{ .reg .u64 t; cvta.to.shared.u64 t, %1; cvt.u32.u64 %0, t; }"
        : "=r"(a) : "l"(p));
    return a;
}

__device__ __forceinline__ void mma_tf32(float* c, const uint4& a, const uint2& b) {
    asm volatile(
        "mma.sync.aligned.m16n8k8.row.col.f32.tf32.tf32.f32 "
        "{%0,%1,%2,%3}, {%4,%5,%6,%7}, {%8,%9}, {%0,%1,%2,%3};\n"
        : "+f"(c[0]), "+f"(c[1]), "+f"(c[2]), "+f"(c[3])
        : "r"(a.x), "r"(a.y), "r"(a.z), "r"(a.w), "r"(b.x), "r"(b.y));
}

// ---------------- pre: self-loop attr = mean of incoming edge_attr ------------
__global__ void k_init_pre() {
    int i = blockIdx.x * blockDim.x + threadIdx.x;
    if (i < NN * BONDD) g_loopsum[i] = 0.f;
    if (i < NN) g_deg[i] = 0.f;
}

__global__ void k_degattr(const int* __restrict__ dst, const float* __restrict__ ea) {
    int j = blockIdx.x * blockDim.x + threadIdx.x;
    if (j >= EE * BONDD) return;
    int e = j / BONDD, b = j - e * BONDD;
    int d = dst[e];
    atomicAdd(&g_loopsum[d * BONDD + b], ea[j]);
    if (b == 0) atomicAdd(&g_deg[d], 1.f);
}

__global__ void k_loopdiv() {
    int j = blockIdx.x * blockDim.x + threadIdx.x;
    if (j >= NN * BONDD) return;
    int n = j / BONDD;
    g_loop[j] = g_loopsum[j] / fmaxf(g_deg[n], 1.f);
}

// ---------------- W -> tf32 B-fragment-major layout ---------------------------
// element (k, n) -> block (n>>3)*32 + (k>>3); lane=(n&7)*4+(k&3); slot=(k>>2)&1
__global__ void k_prepW(const float* __restrict__ Wl, const float* __restrict__ Wr) {
    int z = blockIdx.y;  // 0..9 = l*2+which
    const float* W = ((z & 1) ? Wr : Wl) + (size_t)(z >> 1) * WELEM;
    int idx = blockIdx.x * 256 + threadIdx.x;
    int k = idx >> 11;
    int n = idx & 2047;
    float v = tf32r(W[idx]);
    int blk = (n >> 3) * 32 + (k >> 3);
    int lane = (n & 7) * 4 + (k & 3);
    int slot = (k >> 2) & 1;
    g_Wf[(size_t)z * WELEM + blk * 64 + lane * 2 + slot] = v;
}

// ---------------- atom embedding: relu(LN(x @ W + b)) ------------------------
__global__ void k_embed(const float* __restrict__ x, const float* __restrict__ W,
                        const float* __restrict__ b, const float* __restrict__ g,
                        const float* __restrict__ be) {
    int n = blockIdx.x, tid = threadIdx.x;
    __shared__ float sx[ATOMD];
    __shared__ float rs[8], rq[8];
    if (tid < ATOMD) sx[tid] = x[n * ATOMD + tid];
    __syncthreads();
    float acc = b[tid];
    for (int k = 0; k < ATOMD; k++) acc += sx[k] * W[k * HD + tid];
    float a = acc, q = acc * acc;
    #pragma unroll
    for (int o = 16; o; o >>= 1) {
        a += __shfl_xor_sync(~0u, a, o);
        q += __shfl_xor_sync(~0u, q, o);
    }
    int lane = tid & 31, w = tid >> 5;
    if (!lane) { rs[w] = a; rq[w] = q; }
    __syncthreads();
    float sum = 0.f, sq = 0.f;
    #pragma unroll
    for (int i = 0; i < 8; i++) { sum += rs[i]; sq += rq[i]; }
    float mean = sum * (1.f / HD);
    float var = sq * (1.f / HD) - mean * mean;
    float y = (acc - mean) * rsqrtf(var + 1e-5f) * g[tid] + be[tid];
    y = fmaxf(y, 0.f);
    g_h[n * HD + tid] = y;
    store_frag_h(n, tid, y);
}

// ---------------- tf32 mma GEMM: C = h[8000,256] @ W[256,2048] ----------------
// 128x128 CTA tile, 8 warps (4m x 2n), warp tile 32x64, 2-stage cp.async.
__global__ void __launch_bounds__(256, 2) k_gemm_mma(int l) {
    extern __shared__ uint32_t sm[];
    const int t = threadIdx.x;
    const int warp = t >> 5, lane = t & 31;
    const int wm = warp & 3, wn = warp >> 2;
    const int gr = lane >> 2, tg = lane & 3;
    const int m0 = blockIdx.y * 128, n0 = blockIdx.x * 128;
    const int wi = l * 2 + blockIdx.z;
    float* C = blockIdx.z ? g_xr : g_xl;
    const float* Ab = g_hf + (size_t)(m0 >> 4) * 32 * 128;
    const float* Bb = g_Wf + (size_t)wi * WELEM + (size_t)(n0 >> 3) * 32 * 64;
    const uint32_t sbase = smem_u32(sm);

    float c[2][8][4];
    #pragma unroll
    for (int i = 0; i < 2; i++)
        #pragma unroll
        for (int j = 0; j < 8; j++)
            #pragma unroll
            for (int k = 0; k < 4; k++) c[i][j][k] = 0.f;

    // prefetch stage for k-tile kt into buffer s
    #define PREFETCH(kt, s) do { \
        int kb0 = (kt) * 4; \
        _Pragma("unroll") \
        for (int p = 0; p < 4; p++) { \
            int u = p * 256 + t; \
            int i = u >> 7, q = u & 127; \
            const float* srcA = Ab + (i * 32 + kb0) * 128 + q * 4; \
            CP16(sbase + (s) * 16384 + (i * 512 + q * 4) * 4, srcA); \
        } \
        _Pragma("unroll") \
        for (int p = 0; p < 4; p++) { \
            int u = p * 256 + t; \
            int nb = u >> 6, q = u & 63; \
            const float* srcB = Bb + (nb * 32 + kb0) * 64 + q * 4; \
            CP16(sbase + 32768 + (s) * 16384 + (nb * 256 + q * 4) * 4, srcB); \
        } \
        asm volatile("cp.async.commit_group;" ::: "memory"); \
    } while (0)

    PREFETCH(0, 0);
    for (int kt = 0; kt < 8; kt++) {
        int s = kt & 1;
        if (kt < 7) {
            PREFETCH(kt + 1, s ^ 1);
            asm volatile("cp.async.wait_group 1;" ::: "memory");
        } else {
            asm volatile("cp.async.wait_group 0;" ::: "memory");
        }
        __syncthreads();
        const uint32_t* A = sm + s * 4096;
        const uint32_t* B = sm + 8192 + s * 4096;
        #pragma unroll
        for (int ks = 0; ks < 4; ks++) {
            uint4 a[2];
            a[0] = *(const uint4*)&A[((wm * 2 + 0) * 4 + ks) * 128 + lane * 4];
            a[1] = *(const uint4*)&A[((wm * 2 + 1) * 4 + ks) * 128 + lane * 4];
            uint2 b[8];
            #pragma unroll
            for (int jn = 0; jn < 8; jn++)
                b[jn] = *(const uint2*)&B[((wn * 8 + jn) * 4 + ks) * 64 + lane * 2];
            #pragma unroll
            for (int jn = 0; jn < 8; jn++)
                #pragma unroll
                for (int im = 0; im < 2; im++)
                    mma_tf32(c[im][jn], a[im], b[jn]);
        }
        __syncthreads();
    }
    #undef PREFETCH

    #pragma unroll
    for (int im = 0; im < 2; im++) {
        #pragma unroll
        for (int jn = 0; jn < 8; jn++) {
            int row = m0 + wm * 32 + im * 16 + gr;
            int col = n0 + wn * 64 + jn * 8 + tg * 2;
            if (row < NN)
                *(float2*)&C[(size_t)row * HHD + col] = make_float2(c[im][jn][0], c[im][jn][1]);
            if (row + 8 < NN)
                *(float2*)&C[(size_t)(row + 8) * HHD + col] = make_float2(c[im][jn][2], c[im][jn][3]);
        }
    }
}

// ---------------- per-layer zero/init -----------------------------------------
__global__ void k_init_layer() {
    int i = blockIdx.x * blockDim.x + threadIdx.x;
    if (i < NN * HD) g_out[i] = 0.f;
    if (i < NN * NHEADS) { g_s[i] = 0.f; g_m[i] = ENC_NEG_INF; }
}

// ---------------- edge score --------------------------------------------------
__global__ void k_score(const int* __restrict__ src, const int* __restrict__ dst,
                        const float* __restrict__ edge_attr,
                        const float* __restrict__ We_l, const float* __restrict__ att_l) {
    int e = blockIdx.x, tid = threadIdx.x;
    __shared__ float sea[BONDD];
    __shared__ float wsum[NHEADS * 8];
    int s, d;
    const float* ea;
    if (e < EE) { s = src[e]; d = dst[e]; ea = edge_attr + e * BONDD; }
    else        { s = d = e - EE;          ea = g_loop + (e - EE) * BONDD; }
    if (tid < BONDD) sea[tid] = ea[tid];
    __syncthreads();
    const float* xlrow = g_xl + (size_t)s * HHD;
    const float* xrrow = g_xr + (size_t)d * HHD;
    float part[NHEADS];
    #pragma unroll
    for (int h = 0; h < NHEADS; h++) {
        int cc = h * HD + tid;
        float eev = 0.f;
        #pragma unroll
        for (int b = 0; b < BONDD; b++) eev += sea[b] * We_l[b * HHD + cc];
        float v = xlrow[cc] + xrrow[cc] + eev;
        v = v > 0.f ? v : 0.2f * v;
        part[h] = v * att_l[cc];
    }
    int lane = tid & 31, w = tid >> 5;
    #pragma unroll
    for (int h = 0; h < NHEADS; h++) {
        float v = part[h];
        #pragma unroll
        for (int o = 16; o; o >>= 1) v += __shfl_xor_sync(~0u, v, o);
        if (!lane) wsum[h * 8 + w] = v;
    }
    __syncthreads();
    if (tid < NHEADS) {
        float v = 0.f;
        #pragma unroll
        for (int w2 = 0; w2 < 8; w2++) v += wsum[tid * 8 + w2];
        g_score[e * NHEADS + tid] = v;
        atomicMax(&g_m[d * NHEADS + tid], fenc(v));
    }
}

// ---------------- exp(score - max) + segment sum ------------------------------
__global__ void k_expsum(const int* __restrict__ dst) {
    int j = blockIdx.x * blockDim.x + threadIdx.x;
    if (j >= EAA * NHEADS) return;
    int e = j / NHEADS, h = j - e * NHEADS;
    int d = (e < EE) ? dst[e] : (e - EE);
    float ex = expf(g_score[j] - fdec(g_m[d * NHEADS + h]));
    g_score[j] = ex;
    atomicAdd(&g_s[d * NHEADS + h], ex);
}

// ---------------- message -----------------------------------------------------
__global__ void k_message(const int* __restrict__ src, const int* __restrict__ dst) {
    int e = blockIdx.x, tid = threadIdx.x;
    __shared__ float alpha[NHEADS];
    int s, d;
    if (e < EE) { s = src[e]; d = dst[e]; }
    else        { s = d = e - EE; }
    if (tid < NHEADS)
        alpha[tid] = g_score[e * NHEADS + tid] / g_s[d * NHEADS + tid];
    __syncthreads();
    const float* xlrow = g_xl + (size_t)s * HHD;
    float acc = 0.f;
    #pragma unroll
    for (int h = 0; h < NHEADS; h++) acc += xlrow[h * HD + tid] * alpha[h];
    atomicAdd(&g_out[d * HD + tid], 0.125f * acc);
}

// ---------------- residual + LayerNorm (+ fragment store) ---------------------
__global__ void k_resln(const float* __restrict__ bias_l, const float* __restrict__ g,
                        const float* __restrict__ be) {
    int n = blockIdx.x, tid = threadIdx.x;
    __shared__ float rs[8], rq[8];
    float v = g_out[n * HD + tid] + bias_l[tid] + g_h[n * HD + tid];
    float a = v, q = v * v;
    #pragma unroll
    for (int o = 16; o; o >>= 1) {
        a += __shfl_xor_sync(~0u, a, o);
        q += __shfl_xor_sync(~0u, q, o);
    }
    int lane = tid & 31, w = tid >> 5;
    if (!lane) { rs[w] = a; rq[w] = q; }
    __syncthreads();
    float sum = 0.f, sq = 0.f;
    #pragma unroll
    for (int i = 0; i < 8; i++) { sum += rs[i]; sq += rq[i]; }
    float mean = sum * (1.f / HD);
    float var = sq * (1.f / HD) - mean * mean;
    float y = (v - mean) * rsqrtf(var + 1e-5f) * g[tid] + be[tid];
    g_h[n * HD + tid] = y;
    store_frag_h(n, tid, y);
}

// ---------------- readout -----------------------------------------------------
__global__ void k_initread(float* __restrict__ out) {
    int i = blockIdx.x * blockDim.x + threadIdx.x;
    if (i < BB * HD) out[i] = 0.f;
    if (i < BB) { g_gm[i] = ENC_NEG_INF; g_gs[i] = 0.f; }
}

__global__ void k_gate(const float* __restrict__ W1, const float* __restrict__ b1,
                       const float* __restrict__ W2, const float* __restrict__ b2,
                       const int* __restrict__ batch) {
    int n = blockIdx.x, tid = threadIdx.x;
    __shared__ float sh[HD];
    __shared__ float rs[4];
    sh[tid] = g_h[n * HD + tid];
    sh[tid + 128] = g_h[n * HD + tid + 128];
    __syncthreads();
    float acc = b1[tid];
    for (int k = 0; k < HD; k++) acc += sh[k] * W1[k * 128 + tid];
    float part = fmaxf(acc, 0.f) * W2[tid];
    #pragma unroll
    for (int o = 16; o; o >>= 1) part += __shfl_xor_sync(~0u, part, o);
    int lane = tid & 31, w = tid >> 5;
    if (!lane) rs[w] = part;
    __syncthreads();
    if (tid == 0) {
        float gate = rs[0] + rs[1] + rs[2] + rs[3] + b2[0];
        g_gate[n] = gate;
        atomicMax(&g_gm[batch[n]], fenc(gate));
    }
}

__global__ void k_gexp(const int* __restrict__ batch) {
    int n = blockIdx.x * blockDim.x + threadIdx.x;
    if (n >= NN) return;
    int b = batch[n];
    float ge = expf(g_gate[n] - fdec(g_gm[b]));
    g_ge[n] = ge;
    atomicAdd(&g_gs[b], ge);
}

__global__ void k_readout(const int* __restrict__ batch, float* __restrict__ out) {
    int n = blockIdx.x, tid = threadIdx.x;
    int b = batch[n];
    float w = g_ge[n] / fmaxf(g_gs[b], 1e-16f);
    atomicAdd(&out[b * HD + tid], w * g_h[n * HD + tid]);
}

// ---------------- launcher ----------------------------------------------------
extern "C" void kernel_launch(void* const* d_in, const int* in_sizes, int n_in,
                              void* d_out, int out_size) {
    const float* x         = (const float*)d_in[0];
    const float* edge_attr = (const float*)d_in[1];
    const float* emb_W     = (const float*)d_in[2];
    const float* emb_b     = (const float*)d_in[3];
    const float* emb_g     = (const float*)d_in[4];
    const float* emb_beta  = (const float*)d_in[5];
    const float* Wl        = (const float*)d_in[6];
    const float* Wr        = (const float*)d_in[7];
    const float* We        = (const float*)d_in[8];
    const float* att       = (const float*)d_in[9];
    const float* bias      = (const float*)d_in[10];
    const float* ln_g      = (const float*)d_in[11];
    const float* ln_b      = (const float*)d_in[12];
    const float* g1W       = (const float*)d_in[13];
    const float* g1b       = (const float*)d_in[14];
    const float* g2W       = (const float*)d_in[15];
    const float* g2b       = (const float*)d_in[16];
    const int* edge_index  = (const int*)d_in[17];
    const int* batch       = (const int*)d_in[18];
    const int* src = edge_index;
    const int* dst = edge_index + EE;
    float* out = (float*)d_out;

    cudaFuncSetAttribute(k_gemm_mma, cudaFuncAttributeMaxDynamicSharedMemorySize, 65536);

    k_init_pre<<<(NN * BONDD + 255) / 256, 256>>>();
    k_degattr<<<(EE * BONDD + 255) / 256, 256>>>(dst, edge_attr);
    k_loopdiv<<<(NN * BONDD + 255) / 256, 256>>>();
    k_prepW<<<dim3(WELEM / 256, 10), 256>>>(Wl, Wr);
    k_embed<<<NN, HD>>>(x, emb_W, emb_b, emb_g, emb_beta);

    dim3 gg(HHD / 128, (NN + 127) / 128, 2);
    for (int l = 0; l < NLAYERS; l++) {
        k_init_layer<<<(NN * HD + 255) / 256, 256>>>();
        k_gemm_mma<<<gg, 256, 65536>>>(l);
        k_score<<<EAA, HD>>>(src, dst, edge_attr,
                             We + (size_t)l * BONDD * HHD,
                             att + (size_t)l * NHEADS * HD);
        k_expsum<<<(EAA * NHEADS + 255) / 256, 256>>>(dst);
        k_message<<<EAA, HD>>>(src, dst);
        k_resln<<<NN, HD>>>(bias + l * HD, ln_g + l * HD, ln_b + l * HD);
    }

    k_initread<<<(BB * HD + 255) / 256, 256>>>(out);
    k_gate<<<NN, 128>>>(g1W, g1b, g2W, g2b, batch);
    k_gexp<<<(NN + 255) / 256, 256>>>(batch);
    k_readout<<<NN, HD>>>(batch, out);
}